// round 15
// baseline (speedup 1.0000x reference)
#include <cuda_runtime.h>
#include <cuda_fp16.h>
#include <cstdint>

// ---------------- problem constants ----------------
#define BB      2
#define LL      2048
#define DM      2048
#define HH      64
#define PP      64
#define NST     128
#define KK      4
#define CHUNK   256
#define CC      8            // LL / CHUNK
#define DI      4096         // H*P
#define CONV    4352         // DI + 2*NST
#define PROJ    8512         // DI + CONV + HH
#define EPSV    1e-5f

// ---------------- scratch (static device memory) ---------------------------
__device__ float g_proj[(size_t)BB * LL * PROJ];
__device__ float g_hbc [(size_t)BB * LL * CONV];
__device__ float g_dt  [(size_t)BB * LL * HH];
__device__ float g_cum [(size_t)BB * LL * HH];
__device__ float g_s   [(size_t)BB * CC * CHUNK * CHUNK];
__device__ float g_states[(size_t)BB * CC * HH * PP * NST];
__device__ float g_prev  [(size_t)BB * CC * HH * PP * NST];
__device__ float g_y   [(size_t)BB * LL * DI];
// fp16 staging: A packed per-row k-pairs; W packed [kp][n]
__device__ unsigned g_hA[(size_t)4096 * 2048];
__device__ unsigned g_hW[(size_t)1024 * 8512];

// ---------------- helpers ----------------------------------------------------
__device__ __forceinline__ unsigned h2pack(float lo, float hi) {
    unsigned r;
    asm("cvt.rn.f16x2.f32 %0, %1, %2;" : "=r"(r) : "f"(hi), "f"(lo));
    return r;
}
__device__ __forceinline__ uint32_t sptr(const void* p) {
    return (uint32_t)__cvta_generic_to_shared(p);
}
__device__ __forceinline__ void cp16(uint32_t dst, const void* src, int sz) {
    asm volatile("cp.async.cg.shared.global [%0], [%1], 16, %2;"
                 :: "r"(dst), "l"(src), "r"(sz) : "memory");
}
#define CP_COMMIT() asm volatile("cp.async.commit_group;" ::: "memory")
#define CP_WAIT1()  asm volatile("cp.async.wait_group 1;" ::: "memory")
#define CP_WAIT0()  asm volatile("cp.async.wait_group 0;" ::: "memory")

// ---------------- conversion kernels -----------------------------------------
__global__ void cvtA_kernel(const float* __restrict__ A, unsigned* __restrict__ Ah,
                            size_t total4)
{
    size_t i = (size_t)blockIdx.x * blockDim.x + threadIdx.x;
    if (i >= total4) return;
    float4 v = *(const float4*)&A[i * 4];
    *(uint2*)&Ah[i * 2] = make_uint2(h2pack(v.x, v.y), h2pack(v.z, v.w));
}

__global__ void cvtW_kernel(const float* __restrict__ W, unsigned* __restrict__ Wp,
                            int Kd, int N)
{
    size_t i = (size_t)blockIdx.x * blockDim.x + threadIdx.x;
    size_t total = (size_t)(Kd / 2) * (N / 4);
    if (i >= total) return;
    int n4 = (int)(i % (N / 4)) * 4;
    int kp = (int)(i / (N / 4));
    float4 r0 = *(const float4*)&W[(size_t)(2 * kp) * N + n4];
    float4 r1 = *(const float4*)&W[(size_t)(2 * kp + 1) * N + n4];
    *(uint4*)&Wp[(size_t)kp * N + n4] =
        make_uint4(h2pack(r0.x, r1.x), h2pack(r0.y, r1.y),
                   h2pack(r0.z, r1.z), h2pack(r0.w, r1.w));
}

// ---------------- FP16 GEMM v6: 128 thr, 64x64 warp tiles, 3-stage cp.async --
#define A_STG 2560           // u32 per A stage (128 x 20)
#define B_STG 2176           // u32 per B stage (16 x 136)
#define B_BASE (3 * A_STG)

__global__ __launch_bounds__(128) void fp16_gemm_kernel(
    const unsigned* __restrict__ Ah,   // M x Kd/2 u32
    const unsigned* __restrict__ Bp,   // (Kd/2) x N u32
    float* __restrict__ C, int M, int N, int Kd)
{
    extern __shared__ __align__(16) unsigned smem_u[];
#define ASM(S, MM, KP) (smem_u + (S) * A_STG + (MM) * 20 + (KP))
#define BSM(S, KP, NN) (smem_u + B_BASE + (S) * B_STG + (KP) * 136 + (NN))

    const int tid  = threadIdx.x;
    const int lane = tid & 31;
    const int warp = tid >> 5;           // 0..3
    const int wm = (warp >> 1) * 64;     // 0 / 64
    const int wn = (warp & 1) * 64;      // 0 / 64
    const int row0 = blockIdx.y * 128, col0 = blockIdx.x * 128;

    const int g  = lane >> 2;
    const int t4 = lane & 3;
    const int lm_r  = lane & 15;
    const int lm_kp = (lane >> 4) * 4;

    const int Kp = Kd >> 1;

    // loaders (128 threads)
    const int arow = tid;                // A: one row per thread, 16 u32
    const int bkp = tid >> 4;            // 0..7 (+8)
    const int bn  = (tid & 15) * 8;      // 0..120
    const int bsz0 = ((col0 + bn + 3) < N) ? 16 : 0;
    const int bsz1 = ((col0 + bn + 7) < N) ? 16 : 0;

    float acc[4][8][4];
#pragma unroll
    for (int m = 0; m < 4; m++)
#pragma unroll
        for (int n = 0; n < 8; n++)
#pragma unroll
            for (int q = 0; q < 4; q++) acc[m][n][q] = 0.f;

#define CPLOAD(S, KN)                                                              \
    {                                                                              \
        const unsigned* ap = &Ah[(size_t)(row0 + arow) * Kp + ((KN) >> 1)];        \
        cp16(sptr(ASM(S, arow, 0)),  ap,      16);                                 \
        cp16(sptr(ASM(S, arow, 4)),  ap + 4,  16);                                 \
        cp16(sptr(ASM(S, arow, 8)),  ap + 8,  16);                                 \
        cp16(sptr(ASM(S, arow, 12)), ap + 12, 16);                                 \
        const unsigned* bp = &Bp[(size_t)(((KN) >> 1) + bkp) * N + col0 + bn];     \
        cp16(sptr(BSM(S, bkp, bn)),         bp,                    bsz0);          \
        cp16(sptr(BSM(S, bkp, bn + 4)),     bp + 4,                bsz1);          \
        cp16(sptr(BSM(S, bkp + 8, bn)),     bp + (size_t)8 * N,     bsz0);         \
        cp16(sptr(BSM(S, bkp + 8, bn + 4)), bp + (size_t)8 * N + 4, bsz1);         \
    }

    const int NIT = Kd / 32;
    CPLOAD(0, 0)  CP_COMMIT();
    CPLOAD(1, 32) CP_COMMIT();
    CP_WAIT1();
    __syncthreads();

    for (int it = 0; it < NIT; it++) {
        const int buf = it % 3;

#pragma unroll
        for (int ks = 0; ks < 2; ks++) {
            unsigned af[4][4], bf[8][2];
#pragma unroll
            for (int mt = 0; mt < 4; mt++) {
                uint32_t addr = sptr(ASM(buf, wm + mt * 16 + lm_r, ks * 8 + lm_kp));
                asm volatile(
                    "ldmatrix.sync.aligned.m8n8.x4.shared.b16 {%0,%1,%2,%3}, [%4];"
                    : "=r"(af[mt][0]), "=r"(af[mt][1]),
                      "=r"(af[mt][2]), "=r"(af[mt][3])
                    : "r"(addr));
            }
#pragma unroll
            for (int nt = 0; nt < 8; nt++) {
                int cB = wn + nt * 8 + g;
                bf[nt][0] = *BSM(buf, ks * 8 + t4, cB);
                bf[nt][1] = *BSM(buf, ks * 8 + t4 + 4, cB);
            }
#pragma unroll
            for (int mt = 0; mt < 4; mt++)
#pragma unroll
                for (int nt = 0; nt < 8; nt++) {
                    asm volatile(
                        "mma.sync.aligned.m16n8k16.row.col.f32.f16.f16.f32 "
                        "{%0,%1,%2,%3}, {%4,%5,%6,%7}, {%8,%9}, {%0,%1,%2,%3};"
                        : "+f"(acc[mt][nt][0]), "+f"(acc[mt][nt][1]),
                          "+f"(acc[mt][nt][2]), "+f"(acc[mt][nt][3])
                        : "r"(af[mt][0]), "r"(af[mt][1]),
                          "r"(af[mt][2]), "r"(af[mt][3]),
                          "r"(bf[nt][0]), "r"(bf[nt][1]));
                }
        }

        if (it + 2 < NIT) {
            CPLOAD((it + 2) % 3, (it + 2) * 32)
            CP_COMMIT();
            CP_WAIT1();
            __syncthreads();
        } else if (it + 1 < NIT) {
            CP_WAIT0();
            __syncthreads();
        }
    }

#pragma unroll
    for (int mt = 0; mt < 4; mt++) {
        int r = row0 + wm + mt * 16 + g;
#pragma unroll
        for (int nt = 0; nt < 8; nt++) {
            int cidx = col0 + wn + nt * 8 + t4 * 2;
            if (cidx < N) {
                *(float2*)&C[(size_t)r * N + cidx] = make_float2(acc[mt][nt][0], acc[mt][nt][1]);
                *(float2*)&C[(size_t)(r + 8) * N + cidx] = make_float2(acc[mt][nt][2], acc[mt][nt][3]);
            }
        }
    }
#undef CPLOAD
#undef ASM
#undef BSM
}
#define GEMM_SMEM 56832

// ---------------- conv v2: smem-tiled depthwise conv + bias + SiLU ----------
__global__ __launch_bounds__(256) void conv_silu_kernel(
    const float* __restrict__ conv_w, const float* __restrict__ conv_b)
{
    __shared__ float sm[35][256];
    const int tid = threadIdx.x;
    const int ch  = blockIdx.x * 256 + tid;
    const int l0  = blockIdx.y * 32;
    const int b   = blockIdx.z;

    const float* src = &g_proj[((size_t)b * LL) * PROJ + DI + ch];
#pragma unroll
    for (int r = 0; r < 35; r++) {
        int l = l0 - 3 + r;
        sm[r][tid] = (l >= 0) ? src[(size_t)l * PROJ] : 0.f;
    }
    float4 wv = *(const float4*)&conv_w[ch * 4];
    float bias = conv_b[ch];
    __syncthreads();

    float* dst = &g_hbc[((size_t)b * LL + l0) * CONV + ch];
#pragma unroll
    for (int j = 0; j < 32; j++) {
        float acc = bias;
        acc += sm[j][tid]     * wv.x;
        acc += sm[j + 1][tid] * wv.y;
        acc += sm[j + 2][tid] * wv.z;
        acc += sm[j + 3][tid] * wv.w;
        dst[(size_t)j * CONV] = acc / (1.f + __expf(-acc));
    }
}

// ---------------- dt softplus + chunk cumsum --------------------------------
__global__ void dtcum_kernel(const float* __restrict__ dt_bias,
                             const float* __restrict__ A_log)
{
    int gw   = (blockIdx.x * blockDim.x + threadIdx.x) >> 5;
    int lane = threadIdx.x & 31;
    if (gw >= BB * CC * HH) return;
    int h  = gw % HH;
    int bc = gw / HH;
    int c  = bc % CC;
    int b  = bc / CC;

    float bias = dt_bias[h];
    float Ah   = -__expf(A_log[h]);
    float carry = 0.f;

    for (int t = 0; t < CHUNK / 32; t++) {
        int l = c * CHUNK + t * 32 + lane;
        size_t row = (size_t)b * LL + l;
        float v = g_proj[row * PROJ + DI + CONV + h] + bias;
        float dtv = (v > 20.f) ? v : log1pf(__expf(v));
        g_dt[row * HH + h] = dtv;
        float s = dtv * Ah;
#pragma unroll
        for (int off = 1; off < 32; off <<= 1) {
            float y = __shfl_up_sync(0xffffffffu, s, off);
            if (lane >= off) s += y;
        }
        float cum = carry + s;
        g_cum[row * HH + h] = cum;
        carry = __shfl_sync(0xffffffffu, cum, 31);
    }
}

// ---------------- head-independent scores: s[i,j] = C_i . B_j --------------
__global__ void scores_kernel()
{
    if (blockIdx.y < blockIdx.x) return;
    int bc = blockIdx.z;
    int b = bc / CC, c = bc % CC;
    int i0 = blockIdx.y * 32, j0 = blockIdx.x * 32;

    __shared__ float Cs[32][129];
    __shared__ float Bsh[32][129];

    int tx = threadIdx.x, ty = threadIdx.y;
    size_t baseRow = (size_t)b * LL + c * CHUNK;

#pragma unroll
    for (int q = 0; q < 4; q++) {
        int n = tx + 32 * q;
        Cs[ty][n]  = g_hbc[(baseRow + i0 + ty) * CONV + DI + NST + n];
        Bsh[ty][n] = g_hbc[(baseRow + j0 + ty) * CONV + DI + n];
    }
    __syncthreads();

    float acc = 0.f;
#pragma unroll
    for (int n = 0; n < NST; n++) acc += Cs[ty][n] * Bsh[tx][n];

    g_s[(size_t)bc * CHUNK * CHUNK + (size_t)(i0 + ty) * CHUNK + j0 + tx] = acc;
}

// ---------------- states v3: broadcast LDS.128 B reads ----------------------
__global__ __launch_bounds__(256) void states_kernel()
{
    int bch = blockIdx.x;
    int h  = bch % HH;
    int bc = bch / HH;
    int c  = bc % CC, b = bc / CC;

    __shared__ float xs[32][66];
    __shared__ __align__(16) float Bsh[32][132];
    __shared__ float wsh[32];

    int tid = threadIdx.x;
    int p  = tid & 63;
    int n0 = (tid >> 6) * 32;
    size_t baseRow = (size_t)b * LL + c * CHUNK;
    float cumlast = g_cum[(baseRow + CHUNK - 1) * HH + h];

    float acc[32];
#pragma unroll
    for (int k = 0; k < 32; k++) acc[k] = 0.f;

    for (int lt = 0; lt < CHUNK; lt += 32) {
        for (int q = tid; q < 32 * 64; q += 256) {
            int ll = q >> 6, pp = q & 63;
            xs[ll][pp] = g_hbc[(baseRow + lt + ll) * CONV + h * PP + pp];
        }
        for (int q = tid; q < 32 * 128; q += 256) {
            int ll = q >> 7, nn = q & 127;
            Bsh[ll][nn] = g_hbc[(baseRow + lt + ll) * CONV + DI + nn];
        }
        if (tid < 32) {
            size_t r = baseRow + lt + tid;
            wsh[tid] = __expf(cumlast - g_cum[r * HH + h]) * g_dt[r * HH + h];
        }
        __syncthreads();
#pragma unroll 4
        for (int ll = 0; ll < 32; ll++) {
            float xv = wsh[ll] * xs[ll][p];
            const float4* bp = (const float4*)&Bsh[ll][n0];
#pragma unroll
            for (int j = 0; j < 8; j++) {
                float4 bv = bp[j];
                acc[j*4+0] += xv * bv.x;
                acc[j*4+1] += xv * bv.y;
                acc[j*4+2] += xv * bv.z;
                acc[j*4+3] += xv * bv.w;
            }
        }
        __syncthreads();
    }

    size_t ob = ((size_t)bch * PP + p) * NST + n0;
#pragma unroll
    for (int k = 0; k < 32; k++) g_states[ob + k] = acc[k];
}

// ---------------- inter-chunk scan ------------------------------------------
__global__ void scan_kernel()
{
    int idx = blockIdx.x * blockDim.x + threadIdx.x;
    if (idx >= BB * HH * PP * NST) return;
    int n = idx & 127;
    int p = (idx >> 7) & 63;
    int h = (idx >> 13) & 63;
    int b = idx >> 19;

    float prev = 0.f;
#pragma unroll
    for (int c = 0; c < CC; c++) {
        size_t sidx = ((((size_t)(b * CC + c) * HH + h) * PP + p) * NST) + n;
        g_prev[sidx] = prev;
        float cd = __expf(g_cum[((size_t)b * LL + c * CHUNK + CHUNK - 1) * HH + h]);
        prev = cd * prev + g_states[sidx];
    }
}

// ---------------- ycomb v4: precomputed diag weights + exact zero-skip ------
__global__ __launch_bounds__(256) void ycomb_kernel(const float* __restrict__ D_param)
{
    int blk = blockIdx.x;
    int it  = blk & 3;
    int bch = blk >> 2;
    int h  = bch % HH;
    int bc = bch / HH;
    int c  = bc % CC, b = bc / CC;

    __shared__ float sm[2 * 64 * 68];
    __shared__ float s_cumj[64], s_dtj[64], s_wj[64];
    const int XOFF = 64 * 68;

    const int tid = threadIdx.x;
    const int p0  = (tid & 7) * 8;
    const int ig  = tid >> 3;
    const int il0 = ig * 2, il1 = il0 + 1;

    size_t baseRow = (size_t)b * LL + c * CHUNK;
    const int gi0 = it * 64 + il0;
    const float cumi0 = g_cum[(baseRow + gi0) * HH + h];
    const float cumi1 = g_cum[(baseRow + gi0 + 1) * HH + h];

    float acc0[8], acc1[8];
#pragma unroll
    for (int q = 0; q < 8; q++) { acc0[q] = 0.f; acc1[q] = 0.f; }

    for (int jt = 0; jt <= it; jt++) {
        for (int q = tid; q < 64 * 16; q += 256) {
            int r = q >> 4, c4 = (q & 15) * 4;
            float4 v = *(const float4*)&g_s[((size_t)bc * CHUNK + it * 64 + r) * CHUNK + jt * 64 + c4];
            *(float4*)&sm[r * 68 + c4] = v;
            float4 xv = *(const float4*)&g_hbc[(baseRow + jt * 64 + r) * CONV + h * PP + c4];
            *(float4*)&sm[XOFF + r * 68 + c4] = xv;
        }
        if (tid < 64) {
            size_t r = baseRow + jt * 64 + tid;
            s_cumj[tid] = g_cum[r * HH + h];
            s_dtj[tid]  = g_dt[r * HH + h];
        }
        __syncthreads();
        float cm = s_cumj[63];
        if (jt < it) {
            if (tid < 64)
                s_wj[tid] = __expf(cm - s_cumj[tid]) * s_dtj[tid];
        } else {
            for (int q = tid; q < 64 * 16; q += 256) {
                int r = q >> 4, c4 = (q & 15) * 4;
                float ci = s_cumj[r];
                float* wp = &sm[r * 68 + c4];
                float4 sv = *(float4*)wp;
                float4 wv;
                wv.x = (c4 + 0 <= r) ? sv.x * __expf(ci - s_cumj[c4 + 0]) * s_dtj[c4 + 0] : 0.f;
                wv.y = (c4 + 1 <= r) ? sv.y * __expf(ci - s_cumj[c4 + 1]) * s_dtj[c4 + 1] : 0.f;
                wv.z = (c4 + 2 <= r) ? sv.z * __expf(ci - s_cumj[c4 + 2]) * s_dtj[c4 + 2] : 0.f;
                wv.w = (c4 + 3 <= r) ? sv.w * __expf(ci - s_cumj[c4 + 3]) * s_dtj[c4 + 3] : 0.f;
                *(float4*)wp = wv;
            }
        }
        __syncthreads();

        if (jt < it) {
            float E0 = __expf(cumi0 - cm);
            float E1 = __expf(cumi1 - cm);
#pragma unroll 4
            for (int jj = 0; jj < 64; jj++) {
                float wj = s_wj[jj];
                float w0 = sm[il0 * 68 + jj] * wj * E0;
                float w1 = sm[il1 * 68 + jj] * wj * E1;
                float4 xa = *(const float4*)&sm[XOFF + jj * 68 + p0];
                float4 xb = *(const float4*)&sm[XOFF + jj * 68 + p0 + 4];
                acc0[0] += w0 * xa.x; acc0[1] += w0 * xa.y; acc0[2] += w0 * xa.z; acc0[3] += w0 * xa.w;
                acc0[4] += w0 * xb.x; acc0[5] += w0 * xb.y; acc0[6] += w0 * xb.z; acc0[7] += w0 * xb.w;
                acc1[0] += w1 * xa.x; acc1[1] += w1 * xa.y; acc1[2] += w1 * xa.z; acc1[3] += w1 * xa.w;
                acc1[4] += w1 * xb.x; acc1[5] += w1 * xb.y; acc1[6] += w1 * xb.z; acc1[7] += w1 * xb.w;
            }
        } else {
            for (int jj = 0; jj <= il1; jj++) {
                float w0 = sm[il0 * 68 + jj];
                float w1 = sm[il1 * 68 + jj];
                float4 xa = *(const float4*)&sm[XOFF + jj * 68 + p0];
                float4 xb = *(const float4*)&sm[XOFF + jj * 68 + p0 + 4];
                acc0[0] += w0 * xa.x; acc0[1] += w0 * xa.y; acc0[2] += w0 * xa.z; acc0[3] += w0 * xa.w;
                acc0[4] += w0 * xb.x; acc0[5] += w0 * xb.y; acc0[6] += w0 * xb.z; acc0[7] += w0 * xb.w;
                acc1[0] += w1 * xa.x; acc1[1] += w1 * xa.y; acc1[2] += w1 * xa.z; acc1[3] += w1 * xa.w;
                acc1[4] += w1 * xb.x; acc1[5] += w1 * xb.y; acc1[6] += w1 * xb.z; acc1[7] += w1 * xb.w;
            }
        }
        __syncthreads();
    }

    {
        size_t pbase = (size_t)bch * PP * NST;
        for (int q = tid; q < 64 * 32; q += 256) {
            int p = q >> 5, n4 = (q & 31) * 4;
            float4 v = *(const float4*)&g_prev[pbase + (size_t)p * NST + n4];
            sm[(n4 + 0) * 68 + p] = v.x;
            sm[(n4 + 1) * 68 + p] = v.y;
            sm[(n4 + 2) * 68 + p] = v.z;
            sm[(n4 + 3) * 68 + p] = v.w;
        }
        __syncthreads();

        float e0 = __expf(cumi0);
        float e1 = __expf(cumi1);
        const float* C0 = &g_hbc[(baseRow + gi0) * CONV + DI + NST];
        const float* C1 = C0 + CONV;
#pragma unroll 2
        for (int n = 0; n < NST; n += 4) {
            float4 ca = *(const float4*)&C0[n];
            float4 cb = *(const float4*)&C1[n];
#pragma unroll
            for (int k = 0; k < 4; k++) {
                float cav = (k == 0) ? ca.x : (k == 1) ? ca.y : (k == 2) ? ca.z : ca.w;
                float cbv = (k == 0) ? cb.x : (k == 1) ? cb.y : (k == 2) ? cb.z : cb.w;
                float w0 = e0 * cav, w1 = e1 * cbv;
                const float* xp = &sm[(n + k) * 68 + p0];
                float4 xa = *(const float4*)xp;
                float4 xb = *(const float4*)(xp + 4);
                acc0[0] += w0 * xa.x; acc0[1] += w0 * xa.y; acc0[2] += w0 * xa.z; acc0[3] += w0 * xa.w;
                acc0[4] += w0 * xb.x; acc0[5] += w0 * xb.y; acc0[6] += w0 * xb.z; acc0[7] += w0 * xb.w;
                acc1[0] += w1 * xa.x; acc1[1] += w1 * xa.y; acc1[2] += w1 * xa.z; acc1[3] += w1 * xa.w;
                acc1[4] += w1 * xb.x; acc1[5] += w1 * xb.y; acc1[6] += w1 * xb.z; acc1[7] += w1 * xb.w;
            }
        }
    }

    {
        float Dh = D_param[h];
        const float* x0 = &g_hbc[(baseRow + gi0) * CONV + h * PP + p0];
        const float* x1 = x0 + CONV;
        float* y0 = &g_y[(baseRow + gi0) * DI + h * PP + p0];
        float* y1 = y0 + DI;
        float4 o;
        o = make_float4(acc0[0] + Dh * x0[0], acc0[1] + Dh * x0[1], acc0[2] + Dh * x0[2], acc0[3] + Dh * x0[3]);
        *(float4*)y0 = o;
        o = make_float4(acc0[4] + Dh * x0[4], acc0[5] + Dh * x0[5], acc0[6] + Dh * x0[6], acc0[7] + Dh * x0[7]);
        *(float4*)(y0 + 4) = o;
        o = make_float4(acc1[0] + Dh * x1[0], acc1[1] + Dh * x1[1], acc1[2] + Dh * x1[2], acc1[3] + Dh * x1[3]);
        *(float4*)y1 = o;
        o = make_float4(acc1[4] + Dh * x1[4], acc1[5] + Dh * x1[5], acc1[6] + Dh * x1[6], acc1[7] + Dh * x1[7]);
        *(float4*)(y1 + 4) = o;
    }
}

// ---------------- gated RMSNorm -> packed fp16 directly ----------------------
__global__ __launch_bounds__(256) void gatenorm_kernel(const float* __restrict__ norm_w,
                                                       unsigned* __restrict__ outA)
{
    int row = blockIdx.x;
    __shared__ float sh[DI];
    __shared__ float red[256];

    const float* yrow = &g_y[(size_t)row * DI];
    const float* grow = &g_proj[(size_t)row * PROJ];

    float local = 0.f;
    for (int d = threadIdx.x * 2; d < DI; d += 512) {
        float g0 = grow[d],     g1 = grow[d + 1];
        float hv0 = yrow[d]     * (g0 / (1.f + __expf(-g0)));
        float hv1 = yrow[d + 1] * (g1 / (1.f + __expf(-g1)));
        sh[d] = hv0; sh[d + 1] = hv1;
        local += hv0 * hv0 + hv1 * hv1;
    }
    red[threadIdx.x] = local;
    __syncthreads();
    for (int s = 128; s > 0; s >>= 1) {
        if (threadIdx.x < s) red[threadIdx.x] += red[threadIdx.x + s];
        __syncthreads();
    }
    float rms = rsqrtf(red[0] / (float)DI + EPSV);

    unsigned* orow = &outA[(size_t)row * (DI / 2)];
    for (int d = threadIdx.x * 2; d < DI; d += 512)
        orow[d >> 1] = h2pack(sh[d] * rms * norm_w[d],
                              sh[d + 1] * rms * norm_w[d + 1]);
}

// ---------------- launcher ---------------------------------------------------
extern "C" void kernel_launch(void* const* d_in, const int* in_sizes, int n_in,
                              void* d_out, int out_size)
{
    const float* hs       = (const float*)d_in[0];
    const float* in_proj  = (const float*)d_in[1];
    const float* conv_w   = (const float*)d_in[2];
    const float* conv_b   = (const float*)d_in[3];
    const float* dt_bias  = (const float*)d_in[4];
    const float* A_log    = (const float*)d_in[5];
    const float* D_param  = (const float*)d_in[6];
    const float* norm_w   = (const float*)d_in[7];
    const float* out_proj = (const float*)d_in[8];
    float* out = (float*)d_out;

    float* proj_ptr;   cudaGetSymbolAddress((void**)&proj_ptr, g_proj);
    unsigned* hA_ptr;  cudaGetSymbolAddress((void**)&hA_ptr, g_hA);
    unsigned* hW_ptr;  cudaGetSymbolAddress((void**)&hW_ptr, g_hW);

    cudaFuncSetAttribute(fp16_gemm_kernel,
                         cudaFuncAttributeMaxDynamicSharedMemorySize, GEMM_SMEM);

    const int M = BB * LL;   // 4096

    // 0a) convert activations + in_proj weights to packed fp16
    {
        size_t t4 = (size_t)M * DM / 4;
        cvtA_kernel<<<(unsigned)((t4 + 255) / 256), 256>>>(hs, hA_ptr, t4);
        size_t tw = (size_t)(DM / 2) * (PROJ / 4);
        cvtW_kernel<<<(unsigned)((tw + 255) / 256), 256>>>(in_proj, hW_ptr, DM, PROJ);
    }
    // 1) in-projection GEMM: (4096 x 2048) @ (2048 x 8512)
    {
        dim3 grid((PROJ + 127) / 128, M / 128);
        fp16_gemm_kernel<<<grid, 128, GEMM_SMEM>>>(hA_ptr, hW_ptr, proj_ptr, M, PROJ, DM);
    }
    // 2) depthwise conv + silu (smem-tiled v2)
    {
        dim3 grid(CONV / 256, LL / 32, BB);
        conv_silu_kernel<<<grid, 256>>>(conv_w, conv_b);
    }
    // 3) dt softplus + chunk cumsum
    dtcum_kernel<<<(BB * CC * HH * 32 + 255) / 256, 256>>>(dt_bias, A_log);
    // 4) head-independent CB scores
    {
        dim3 grid(CHUNK / 32, CHUNK / 32, BB * CC);
        scores_kernel<<<grid, dim3(32, 32)>>>();
    }
    // 5) per-chunk states
    states_kernel<<<BB * CC * HH, 256>>>();
    // 6) inter-chunk scan
    scan_kernel<<<(BB * HH * PP * NST + 255) / 256, 256>>>();
    // 7) Y = diag + off + D*x  (v4: zero-skip diag)
    ycomb_kernel<<<BB * CC * HH * 4, 256>>>(D_param);
    // 8) gated RMSNorm -> packed fp16 into g_hA
    gatenorm_kernel<<<BB * LL, 256>>>(norm_w, hA_ptr);
    // 0b) convert out_proj weights
    {
        size_t tw = (size_t)(DI / 2) * (DM / 4);
        cvtW_kernel<<<(unsigned)((tw + 255) / 256), 256>>>(out_proj, hW_ptr, DI, DM);
    }
    // 9) out-projection GEMM: (4096 x 4096) @ (4096 x 2048) -> d_out
    {
        dim3 grid(DM / 128, M / 128);
        fp16_gemm_kernel<<<grid, 128, GEMM_SMEM>>>(hA_ptr, hW_ptr, out, M, DM, DI);
    }
    (void)in_sizes; (void)n_in; (void)out_size;
}

// round 16
// speedup vs baseline: 1.1754x; 1.1754x over previous
#include <cuda_runtime.h>
#include <cuda_fp16.h>
#include <cstdint>

// ---------------- problem constants ----------------
#define BB      2
#define LL      2048
#define DM      2048
#define HH      64
#define PP      64
#define NST     128
#define KK      4
#define CHUNK   256
#define CC      8            // LL / CHUNK
#define DI      4096         // H*P
#define CONV    4352         // DI + 2*NST
#define PROJ    8512         // DI + CONV + HH
#define EPSV    1e-5f

// ---------------- scratch (static device memory) ---------------------------
__device__ float g_proj[(size_t)BB * LL * PROJ];
__device__ float g_hbc [(size_t)BB * LL * CONV];
__device__ float g_dt  [(size_t)BB * LL * HH];
__device__ float g_cum [(size_t)BB * LL * HH];
__device__ float g_s   [(size_t)BB * CC * CHUNK * CHUNK];
__device__ float g_states[(size_t)BB * CC * HH * PP * NST];
__device__ float g_prev  [(size_t)BB * CC * HH * PP * NST];
__device__ float g_y   [(size_t)BB * LL * DI];
// fp16 staging: A packed per-row k-pairs; W packed [kp][n]
__device__ unsigned g_hA[(size_t)4096 * 2048];
__device__ unsigned g_hW[(size_t)1024 * 8512];

// ---------------- helpers ----------------------------------------------------
__device__ __forceinline__ unsigned h2pack(float lo, float hi) {
    unsigned r;
    asm("cvt.rn.f16x2.f32 %0, %1, %2;" : "=r"(r) : "f"(hi), "f"(lo));
    return r;
}
__device__ __forceinline__ uint32_t sptr(const void* p) {
    return (uint32_t)__cvta_generic_to_shared(p);
}
__device__ __forceinline__ void cp16(uint32_t dst, const void* src, int sz) {
    asm volatile("cp.async.cg.shared.global [%0], [%1], 16, %2;"
                 :: "r"(dst), "l"(src), "r"(sz) : "memory");
}
#define CP_COMMIT() asm volatile("cp.async.commit_group;" ::: "memory")
#define CP_WAIT1()  asm volatile("cp.async.wait_group 1;" ::: "memory")
#define CP_WAIT0()  asm volatile("cp.async.wait_group 0;" ::: "memory")

// ---------------- conversion kernels -----------------------------------------
__global__ void cvtA_kernel(const float* __restrict__ A, unsigned* __restrict__ Ah,
                            size_t total4)
{
    size_t i = (size_t)blockIdx.x * blockDim.x + threadIdx.x;
    if (i >= total4) return;
    float4 v = *(const float4*)&A[i * 4];
    *(uint2*)&Ah[i * 2] = make_uint2(h2pack(v.x, v.y), h2pack(v.z, v.w));
}

__global__ void cvtW_kernel(const float* __restrict__ W, unsigned* __restrict__ Wp,
                            int Kd, int N)
{
    size_t i = (size_t)blockIdx.x * blockDim.x + threadIdx.x;
    size_t total = (size_t)(Kd / 2) * (N / 4);
    if (i >= total) return;
    int n4 = (int)(i % (N / 4)) * 4;
    int kp = (int)(i / (N / 4));
    float4 r0 = *(const float4*)&W[(size_t)(2 * kp) * N + n4];
    float4 r1 = *(const float4*)&W[(size_t)(2 * kp + 1) * N + n4];
    *(uint4*)&Wp[(size_t)kp * N + n4] =
        make_uint4(h2pack(r0.x, r1.x), h2pack(r0.y, r1.y),
                   h2pack(r0.z, r1.z), h2pack(r0.w, r1.w));
}

// ---------------- FP16 GEMM (R14 exact): 256 thr, 64x32 warp tiles, ----------
// 3-stage cp.async pipeline + ldmatrix A fragments.
#define A_STG 2560           // u32 per A stage (128 x 20)
#define B_STG 2176           // u32 per B stage (16 x 136)
#define B_BASE (3 * A_STG)

__global__ __launch_bounds__(256) void fp16_gemm_kernel(
    const unsigned* __restrict__ Ah,   // M x Kd/2 u32
    const unsigned* __restrict__ Bp,   // (Kd/2) x N u32
    float* __restrict__ C, int M, int N, int Kd)
{
    extern __shared__ __align__(16) unsigned smem_u[];
#define ASM(S, MM, KP) (smem_u + (S) * A_STG + (MM) * 20 + (KP))
#define BSM(S, KP, NN) (smem_u + B_BASE + (S) * B_STG + (KP) * 136 + (NN))

    const int tid  = threadIdx.x;
    const int lane = tid & 31;
    const int warp = tid >> 5;
    const int wm = (warp >> 2) * 64;
    const int wn = (warp & 3) * 32;
    const int row0 = blockIdx.y * 128, col0 = blockIdx.x * 128;

    const int g  = lane >> 2;
    const int t4 = lane & 3;
    const int lm_r  = lane & 15;
    const int lm_kp = (lane >> 4) * 4;

    const int Kp = Kd >> 1;

    const int arow = tid >> 1;
    const int aseg = (tid & 1) * 8;
    const int bkp = tid >> 5;
    const int bn  = (tid & 31) * 4;
    const int bsz = ((col0 + bn + 3) < N) ? 16 : 0;

    float acc[4][4][4];
#pragma unroll
    for (int m = 0; m < 4; m++)
#pragma unroll
        for (int n = 0; n < 4; n++)
#pragma unroll
            for (int q = 0; q < 4; q++) acc[m][n][q] = 0.f;

#define CPLOAD(S, KN)                                                              \
    {                                                                              \
        const unsigned* ap = &Ah[(size_t)(row0 + arow) * Kp + ((KN) >> 1) + aseg]; \
        cp16(sptr(ASM(S, arow, aseg)), ap, 16);                                    \
        cp16(sptr(ASM(S, arow, aseg + 4)), ap + 4, 16);                            \
        const unsigned* bp = &Bp[(size_t)(((KN) >> 1) + bkp) * N + col0 + bn];     \
        cp16(sptr(BSM(S, bkp, bn)), bp, bsz);                                      \
        cp16(sptr(BSM(S, bkp + 8, bn)), bp + (size_t)8 * N, bsz);                  \
    }

    const int NIT = Kd / 32;
    CPLOAD(0, 0)  CP_COMMIT();
    CPLOAD(1, 32) CP_COMMIT();
    CP_WAIT1();
    __syncthreads();

    for (int it = 0; it < NIT; it++) {
        const int buf = it % 3;

#pragma unroll
        for (int ks = 0; ks < 2; ks++) {
            unsigned af[4][4], bf[4][2];
#pragma unroll
            for (int mt = 0; mt < 4; mt++) {
                uint32_t addr = sptr(ASM(buf, wm + mt * 16 + lm_r, ks * 8 + lm_kp));
                asm volatile(
                    "ldmatrix.sync.aligned.m8n8.x4.shared.b16 {%0,%1,%2,%3}, [%4];"
                    : "=r"(af[mt][0]), "=r"(af[mt][1]),
                      "=r"(af[mt][2]), "=r"(af[mt][3])
                    : "r"(addr));
            }
#pragma unroll
            for (int nt = 0; nt < 4; nt++) {
                int cB = wn + nt * 8 + g;
                bf[nt][0] = *BSM(buf, ks * 8 + t4, cB);
                bf[nt][1] = *BSM(buf, ks * 8 + t4 + 4, cB);
            }
#pragma unroll
            for (int mt = 0; mt < 4; mt++)
#pragma unroll
                for (int nt = 0; nt < 4; nt++) {
                    asm volatile(
                        "mma.sync.aligned.m16n8k16.row.col.f32.f16.f16.f32 "
                        "{%0,%1,%2,%3}, {%4,%5,%6,%7}, {%8,%9}, {%0,%1,%2,%3};"
                        : "+f"(acc[mt][nt][0]), "+f"(acc[mt][nt][1]),
                          "+f"(acc[mt][nt][2]), "+f"(acc[mt][nt][3])
                        : "r"(af[mt][0]), "r"(af[mt][1]),
                          "r"(af[mt][2]), "r"(af[mt][3]),
                          "r"(bf[nt][0]), "r"(bf[nt][1]));
                }
        }

        if (it + 2 < NIT) {
            CPLOAD((it + 2) % 3, (it + 2) * 32)
            CP_COMMIT();
            CP_WAIT1();
            __syncthreads();
        } else if (it + 1 < NIT) {
            CP_WAIT0();
            __syncthreads();
        }
    }

#pragma unroll
    for (int mt = 0; mt < 4; mt++) {
        int r = row0 + wm + mt * 16 + g;
#pragma unroll
        for (int nt = 0; nt < 4; nt++) {
            int cidx = col0 + wn + nt * 8 + t4 * 2;
            if (cidx < N) {
                *(float2*)&C[(size_t)r * N + cidx] = make_float2(acc[mt][nt][0], acc[mt][nt][1]);
                *(float2*)&C[(size_t)(r + 8) * N + cidx] = make_float2(acc[mt][nt][2], acc[mt][nt][3]);
            }
        }
    }
#undef CPLOAD
#undef ASM
#undef BSM
}
#define GEMM_SMEM 56832

// ---------------- conv v2: smem-tiled depthwise conv + bias + SiLU ----------
__global__ __launch_bounds__(256) void conv_silu_kernel(
    const float* __restrict__ conv_w, const float* __restrict__ conv_b)
{
    __shared__ float sm[35][256];
    const int tid = threadIdx.x;
    const int ch  = blockIdx.x * 256 + tid;
    const int l0  = blockIdx.y * 32;
    const int b   = blockIdx.z;

    const float* src = &g_proj[((size_t)b * LL) * PROJ + DI + ch];
#pragma unroll
    for (int r = 0; r < 35; r++) {
        int l = l0 - 3 + r;
        sm[r][tid] = (l >= 0) ? src[(size_t)l * PROJ] : 0.f;
    }
    float4 wv = *(const float4*)&conv_w[ch * 4];
    float bias = conv_b[ch];
    __syncthreads();

    float* dst = &g_hbc[((size_t)b * LL + l0) * CONV + ch];
#pragma unroll
    for (int j = 0; j < 32; j++) {
        float acc = bias;
        acc += sm[j][tid]     * wv.x;
        acc += sm[j + 1][tid] * wv.y;
        acc += sm[j + 2][tid] * wv.z;
        acc += sm[j + 3][tid] * wv.w;
        dst[(size_t)j * CONV] = acc / (1.f + __expf(-acc));
    }
}

// ---------------- dt softplus + chunk cumsum --------------------------------
__global__ void dtcum_kernel(const float* __restrict__ dt_bias,
                             const float* __restrict__ A_log)
{
    int gw   = (blockIdx.x * blockDim.x + threadIdx.x) >> 5;
    int lane = threadIdx.x & 31;
    if (gw >= BB * CC * HH) return;
    int h  = gw % HH;
    int bc = gw / HH;
    int c  = bc % CC;
    int b  = bc / CC;

    float bias = dt_bias[h];
    float Ah   = -__expf(A_log[h]);
    float carry = 0.f;

    for (int t = 0; t < CHUNK / 32; t++) {
        int l = c * CHUNK + t * 32 + lane;
        size_t row = (size_t)b * LL + l;
        float v = g_proj[row * PROJ + DI + CONV + h] + bias;
        float dtv = (v > 20.f) ? v : log1pf(__expf(v));
        g_dt[row * HH + h] = dtv;
        float s = dtv * Ah;
#pragma unroll
        for (int off = 1; off < 32; off <<= 1) {
            float y = __shfl_up_sync(0xffffffffu, s, off);
            if (lane >= off) s += y;
        }
        float cum = carry + s;
        g_cum[row * HH + h] = cum;
        carry = __shfl_sync(0xffffffffu, cum, 31);
    }
}

// ---------------- scores: triangular launch ----------------------------------
// blockIdx.x = linear lower-triangular tile index t in [0, 36):
// decode row r = largest with r(r+1)/2 <= t, col = t - r(r+1)/2.
__global__ void scores_kernel()
{
    int t = blockIdx.x;
    // decode triangular index (8 tile-rows)
    int r = (int)((sqrtf(8.f * t + 1.f) - 1.f) * 0.5f);
    while ((r + 1) * (r + 2) / 2 <= t) r++;     // guard fp rounding
    while (r * (r + 1) / 2 > t) r--;
    int cidx = t - r * (r + 1) / 2;

    int bc = blockIdx.z;
    int b = bc / CC, c = bc % CC;
    int i0 = r * 32, j0 = cidx * 32;

    __shared__ float Cs[32][129];
    __shared__ float Bsh[32][129];

    int tx = threadIdx.x, ty = threadIdx.y;
    size_t baseRow = (size_t)b * LL + c * CHUNK;

#pragma unroll
    for (int q = 0; q < 4; q++) {
        int n = tx + 32 * q;
        Cs[ty][n]  = g_hbc[(baseRow + i0 + ty) * CONV + DI + NST + n];
        Bsh[ty][n] = g_hbc[(baseRow + j0 + ty) * CONV + DI + n];
    }
    __syncthreads();

    float acc = 0.f;
#pragma unroll
    for (int n = 0; n < NST; n++) acc += Cs[ty][n] * Bsh[tx][n];

    g_s[(size_t)bc * CHUNK * CHUNK + (size_t)(i0 + ty) * CHUNK + j0 + tx] = acc;
}

// ---------------- states v3: broadcast LDS.128 B reads ----------------------
__global__ __launch_bounds__(256) void states_kernel()
{
    int bch = blockIdx.x;
    int h  = bch % HH;
    int bc = bch / HH;
    int c  = bc % CC, b = bc / CC;

    __shared__ float xs[32][66];
    __shared__ __align__(16) float Bsh[32][132];
    __shared__ float wsh[32];

    int tid = threadIdx.x;
    int p  = tid & 63;
    int n0 = (tid >> 6) * 32;
    size_t baseRow = (size_t)b * LL + c * CHUNK;
    float cumlast = g_cum[(baseRow + CHUNK - 1) * HH + h];

    float acc[32];
#pragma unroll
    for (int k = 0; k < 32; k++) acc[k] = 0.f;

    for (int lt = 0; lt < CHUNK; lt += 32) {
        for (int q = tid; q < 32 * 64; q += 256) {
            int ll = q >> 6, pp = q & 63;
            xs[ll][pp] = g_hbc[(baseRow + lt + ll) * CONV + h * PP + pp];
        }
        for (int q = tid; q < 32 * 128; q += 256) {
            int ll = q >> 7, nn = q & 127;
            Bsh[ll][nn] = g_hbc[(baseRow + lt + ll) * CONV + DI + nn];
        }
        if (tid < 32) {
            size_t r = baseRow + lt + tid;
            wsh[tid] = __expf(cumlast - g_cum[r * HH + h]) * g_dt[r * HH + h];
        }
        __syncthreads();
#pragma unroll 4
        for (int ll = 0; ll < 32; ll++) {
            float xv = wsh[ll] * xs[ll][p];
            const float4* bp = (const float4*)&Bsh[ll][n0];
#pragma unroll
            for (int j = 0; j < 8; j++) {
                float4 bv = bp[j];
                acc[j*4+0] += xv * bv.x;
                acc[j*4+1] += xv * bv.y;
                acc[j*4+2] += xv * bv.z;
                acc[j*4+3] += xv * bv.w;
            }
        }
        __syncthreads();
    }

    size_t ob = ((size_t)bch * PP + p) * NST + n0;
#pragma unroll
    for (int k = 0; k < 32; k++) g_states[ob + k] = acc[k];
}

// ---------------- inter-chunk scan ------------------------------------------
__global__ void scan_kernel()
{
    int idx = blockIdx.x * blockDim.x + threadIdx.x;
    if (idx >= BB * HH * PP * NST) return;
    int n = idx & 127;
    int p = (idx >> 7) & 63;
    int h = (idx >> 13) & 63;
    int b = idx >> 19;

    float prev = 0.f;
#pragma unroll
    for (int c = 0; c < CC; c++) {
        size_t sidx = ((((size_t)(b * CC + c) * HH + h) * PP + p) * NST) + n;
        g_prev[sidx] = prev;
        float cd = __expf(g_cum[((size_t)b * LL + c * CHUNK + CHUNK - 1) * HH + h]);
        prev = cd * prev + g_states[sidx];
    }
}

// ---------------- ycomb v4: precomputed diag weights + exact zero-skip ------
__global__ __launch_bounds__(256) void ycomb_kernel(const float* __restrict__ D_param)
{
    int blk = blockIdx.x;
    int it  = blk & 3;
    int bch = blk >> 2;
    int h  = bch % HH;
    int bc = bch / HH;
    int c  = bc % CC, b = bc / CC;

    __shared__ float sm[2 * 64 * 68];
    __shared__ float s_cumj[64], s_dtj[64], s_wj[64];
    const int XOFF = 64 * 68;

    const int tid = threadIdx.x;
    const int p0  = (tid & 7) * 8;
    const int ig  = tid >> 3;
    const int il0 = ig * 2, il1 = il0 + 1;

    size_t baseRow = (size_t)b * LL + c * CHUNK;
    const int gi0 = it * 64 + il0;
    const float cumi0 = g_cum[(baseRow + gi0) * HH + h];
    const float cumi1 = g_cum[(baseRow + gi0 + 1) * HH + h];

    float acc0[8], acc1[8];
#pragma unroll
    for (int q = 0; q < 8; q++) { acc0[q] = 0.f; acc1[q] = 0.f; }

    for (int jt = 0; jt <= it; jt++) {
        for (int q = tid; q < 64 * 16; q += 256) {
            int r = q >> 4, c4 = (q & 15) * 4;
            float4 v = *(const float4*)&g_s[((size_t)bc * CHUNK + it * 64 + r) * CHUNK + jt * 64 + c4];
            *(float4*)&sm[r * 68 + c4] = v;
            float4 xv = *(const float4*)&g_hbc[(baseRow + jt * 64 + r) * CONV + h * PP + c4];
            *(float4*)&sm[XOFF + r * 68 + c4] = xv;
        }
        if (tid < 64) {
            size_t r = baseRow + jt * 64 + tid;
            s_cumj[tid] = g_cum[r * HH + h];
            s_dtj[tid]  = g_dt[r * HH + h];
        }
        __syncthreads();
        float cm = s_cumj[63];
        if (jt < it) {
            if (tid < 64)
                s_wj[tid] = __expf(cm - s_cumj[tid]) * s_dtj[tid];
        } else {
            for (int q = tid; q < 64 * 16; q += 256) {
                int r = q >> 4, c4 = (q & 15) * 4;
                float ci = s_cumj[r];
                float* wp = &sm[r * 68 + c4];
                float4 sv = *(float4*)wp;
                float4 wv;
                wv.x = (c4 + 0 <= r) ? sv.x * __expf(ci - s_cumj[c4 + 0]) * s_dtj[c4 + 0] : 0.f;
                wv.y = (c4 + 1 <= r) ? sv.y * __expf(ci - s_cumj[c4 + 1]) * s_dtj[c4 + 1] : 0.f;
                wv.z = (c4 + 2 <= r) ? sv.z * __expf(ci - s_cumj[c4 + 2]) * s_dtj[c4 + 2] : 0.f;
                wv.w = (c4 + 3 <= r) ? sv.w * __expf(ci - s_cumj[c4 + 3]) * s_dtj[c4 + 3] : 0.f;
                *(float4*)wp = wv;
            }
        }
        __syncthreads();

        if (jt < it) {
            float E0 = __expf(cumi0 - cm);
            float E1 = __expf(cumi1 - cm);
#pragma unroll 4
            for (int jj = 0; jj < 64; jj++) {
                float wj = s_wj[jj];
                float w0 = sm[il0 * 68 + jj] * wj * E0;
                float w1 = sm[il1 * 68 + jj] * wj * E1;
                float4 xa = *(const float4*)&sm[XOFF + jj * 68 + p0];
                float4 xb = *(const float4*)&sm[XOFF + jj * 68 + p0 + 4];
                acc0[0] += w0 * xa.x; acc0[1] += w0 * xa.y; acc0[2] += w0 * xa.z; acc0[3] += w0 * xa.w;
                acc0[4] += w0 * xb.x; acc0[5] += w0 * xb.y; acc0[6] += w0 * xb.z; acc0[7] += w0 * xb.w;
                acc1[0] += w1 * xa.x; acc1[1] += w1 * xa.y; acc1[2] += w1 * xa.z; acc1[3] += w1 * xa.w;
                acc1[4] += w1 * xb.x; acc1[5] += w1 * xb.y; acc1[6] += w1 * xb.z; acc1[7] += w1 * xb.w;
            }
        } else {
            for (int jj = 0; jj <= il1; jj++) {
                float w0 = sm[il0 * 68 + jj];
                float w1 = sm[il1 * 68 + jj];
                float4 xa = *(const float4*)&sm[XOFF + jj * 68 + p0];
                float4 xb = *(const float4*)&sm[XOFF + jj * 68 + p0 + 4];
                acc0[0] += w0 * xa.x; acc0[1] += w0 * xa.y; acc0[2] += w0 * xa.z; acc0[3] += w0 * xa.w;
                acc0[4] += w0 * xb.x; acc0[5] += w0 * xb.y; acc0[6] += w0 * xb.z; acc0[7] += w0 * xb.w;
                acc1[0] += w1 * xa.x; acc1[1] += w1 * xa.y; acc1[2] += w1 * xa.z; acc1[3] += w1 * xa.w;
                acc1[4] += w1 * xb.x; acc1[5] += w1 * xb.y; acc1[6] += w1 * xb.z; acc1[7] += w1 * xb.w;
            }
        }
        __syncthreads();
    }

    {
        size_t pbase = (size_t)bch * PP * NST;
        for (int q = tid; q < 64 * 32; q += 256) {
            int p = q >> 5, n4 = (q & 31) * 4;
            float4 v = *(const float4*)&g_prev[pbase + (size_t)p * NST + n4];
            sm[(n4 + 0) * 68 + p] = v.x;
            sm[(n4 + 1) * 68 + p] = v.y;
            sm[(n4 + 2) * 68 + p] = v.z;
            sm[(n4 + 3) * 68 + p] = v.w;
        }
        __syncthreads();

        float e0 = __expf(cumi0);
        float e1 = __expf(cumi1);
        const float* C0 = &g_hbc[(baseRow + gi0) * CONV + DI + NST];
        const float* C1 = C0 + CONV;
#pragma unroll 2
        for (int n = 0; n < NST; n += 4) {
            float4 ca = *(const float4*)&C0[n];
            float4 cb = *(const float4*)&C1[n];
#pragma unroll
            for (int k = 0; k < 4; k++) {
                float cav = (k == 0) ? ca.x : (k == 1) ? ca.y : (k == 2) ? ca.z : ca.w;
                float cbv = (k == 0) ? cb.x : (k == 1) ? cb.y : (k == 2) ? cb.z : cb.w;
                float w0 = e0 * cav, w1 = e1 * cbv;
                const float* xp = &sm[(n + k) * 68 + p0];
                float4 xa = *(const float4*)xp;
                float4 xb = *(const float4*)(xp + 4);
                acc0[0] += w0 * xa.x; acc0[1] += w0 * xa.y; acc0[2] += w0 * xa.z; acc0[3] += w0 * xa.w;
                acc0[4] += w0 * xb.x; acc0[5] += w0 * xb.y; acc0[6] += w0 * xb.z; acc0[7] += w0 * xb.w;
                acc1[0] += w1 * xa.x; acc1[1] += w1 * xa.y; acc1[2] += w1 * xa.z; acc1[3] += w1 * xa.w;
                acc1[4] += w1 * xb.x; acc1[5] += w1 * xb.y; acc1[6] += w1 * xb.z; acc1[7] += w1 * xb.w;
            }
        }
    }

    {
        float Dh = D_param[h];
        const float* x0 = &g_hbc[(baseRow + gi0) * CONV + h * PP + p0];
        const float* x1 = x0 + CONV;
        float* y0 = &g_y[(baseRow + gi0) * DI + h * PP + p0];
        float* y1 = y0 + DI;
        float4 o;
        o = make_float4(acc0[0] + Dh * x0[0], acc0[1] + Dh * x0[1], acc0[2] + Dh * x0[2], acc0[3] + Dh * x0[3]);
        *(float4*)y0 = o;
        o = make_float4(acc0[4] + Dh * x0[4], acc0[5] + Dh * x0[5], acc0[6] + Dh * x0[6], acc0[7] + Dh * x0[7]);
        *(float4*)(y0 + 4) = o;
        o = make_float4(acc1[0] + Dh * x1[0], acc1[1] + Dh * x1[1], acc1[2] + Dh * x1[2], acc1[3] + Dh * x1[3]);
        *(float4*)y1 = o;
        o = make_float4(acc1[4] + Dh * x1[4], acc1[5] + Dh * x1[5], acc1[6] + Dh * x1[6], acc1[7] + Dh * x1[7]);
        *(float4*)(y1 + 4) = o;
    }
}

// ---------------- gated RMSNorm -> packed fp16 directly ----------------------
__global__ __launch_bounds__(256) void gatenorm_kernel(const float* __restrict__ norm_w,
                                                       unsigned* __restrict__ outA)
{
    int row = blockIdx.x;
    __shared__ float sh[DI];
    __shared__ float red[256];

    const float* yrow = &g_y[(size_t)row * DI];
    const float* grow = &g_proj[(size_t)row * PROJ];

    float local = 0.f;
    for (int d = threadIdx.x * 2; d < DI; d += 512) {
        float g0 = grow[d],     g1 = grow[d + 1];
        float hv0 = yrow[d]     * (g0 / (1.f + __expf(-g0)));
        float hv1 = yrow[d + 1] * (g1 / (1.f + __expf(-g1)));
        sh[d] = hv0; sh[d + 1] = hv1;
        local += hv0 * hv0 + hv1 * hv1;
    }
    red[threadIdx.x] = local;
    __syncthreads();
    for (int s = 128; s > 0; s >>= 1) {
        if (threadIdx.x < s) red[threadIdx.x] += red[threadIdx.x + s];
        __syncthreads();
    }
    float rms = rsqrtf(red[0] / (float)DI + EPSV);

    unsigned* orow = &outA[(size_t)row * (DI / 2)];
    for (int d = threadIdx.x * 2; d < DI; d += 512)
        orow[d >> 1] = h2pack(sh[d] * rms * norm_w[d],
                              sh[d + 1] * rms * norm_w[d + 1]);
}

// ---------------- launcher ---------------------------------------------------
extern "C" void kernel_launch(void* const* d_in, const int* in_sizes, int n_in,
                              void* d_out, int out_size)
{
    const float* hs       = (const float*)d_in[0];
    const float* in_proj  = (const float*)d_in[1];
    const float* conv_w   = (const float*)d_in[2];
    const float* conv_b   = (const float*)d_in[3];
    const float* dt_bias  = (const float*)d_in[4];
    const float* A_log    = (const float*)d_in[5];
    const float* D_param  = (const float*)d_in[6];
    const float* norm_w   = (const float*)d_in[7];
    const float* out_proj = (const float*)d_in[8];
    float* out = (float*)d_out;

    float* proj_ptr;   cudaGetSymbolAddress((void**)&proj_ptr, g_proj);
    unsigned* hA_ptr;  cudaGetSymbolAddress((void**)&hA_ptr, g_hA);
    unsigned* hW_ptr;  cudaGetSymbolAddress((void**)&hW_ptr, g_hW);

    cudaFuncSetAttribute(fp16_gemm_kernel,
                         cudaFuncAttributeMaxDynamicSharedMemorySize, GEMM_SMEM);

    const int M = BB * LL;   // 4096

    // 0a) convert activations + in_proj weights to packed fp16
    {
        size_t t4 = (size_t)M * DM / 4;
        cvtA_kernel<<<(unsigned)((t4 + 255) / 256), 256>>>(hs, hA_ptr, t4);
        size_t tw = (size_t)(DM / 2) * (PROJ / 4);
        cvtW_kernel<<<(unsigned)((tw + 255) / 256), 256>>>(in_proj, hW_ptr, DM, PROJ);
    }
    // 1) in-projection GEMM: (4096 x 2048) @ (2048 x 8512)
    {
        dim3 grid((PROJ + 127) / 128, M / 128);
        fp16_gemm_kernel<<<grid, 256, GEMM_SMEM>>>(hA_ptr, hW_ptr, proj_ptr, M, PROJ, DM);
    }
    // 2) depthwise conv + silu (smem-tiled v2)
    {
        dim3 grid(CONV / 256, LL / 32, BB);
        conv_silu_kernel<<<grid, 256>>>(conv_w, conv_b);
    }
    // 3) dt softplus + chunk cumsum
    dtcum_kernel<<<(BB * CC * HH * 32 + 255) / 256, 256>>>(dt_bias, A_log);
    // 4) head-independent CB scores (triangular launch: 36 tiles per (b,c))
    {
        dim3 grid(36, 1, BB * CC);
        scores_kernel<<<grid, dim3(32, 32)>>>();
    }
    // 5) per-chunk states
    states_kernel<<<BB * CC * HH, 256>>>();
    // 6) inter-chunk scan
    scan_kernel<<<(BB * HH * PP * NST + 255) / 256, 256>>>();
    // 7) Y = diag + off + D*x  (v4: zero-skip diag)
    ycomb_kernel<<<BB * CC * HH * 4, 256>>>(D_param);
    // 8) gated RMSNorm -> packed fp16 into g_hA
    gatenorm_kernel<<<BB * LL, 256>>>(norm_w, hA_ptr);
    // 0b) convert out_proj weights
    {
        size_t tw = (size_t)(DI / 2) * (DM / 4);
        cvtW_kernel<<<(unsigned)((tw + 255) / 256), 256>>>(out_proj, hW_ptr, DI, DM);
    }
    // 9) out-projection GEMM: (4096 x 4096) @ (4096 x 2048) -> d_out
    {
        dim3 grid(DM / 128, M / 128);
        fp16_gemm_kernel<<<grid, 256, GEMM_SMEM>>>(hA_ptr, hW_ptr, out, M, DM, DI);
    }
    (void)in_sizes; (void)n_in; (void)out_size;
}